// round 3
// baseline (speedup 1.0000x reference)
#include <cuda_runtime.h>
#include <math.h>

#define B_    2048
#define L_    30
#define D_    512
#define X_    512
#define H_    4
#define OUT_  512
#define ITER_ 4

#define RSP    516   // rs row stride in floats (512 + 4 pad, 16B-aligned rows)
#define RSP4   129   // in float4
#define W1SP   132   // w1s row stride in floats (128 + 4 pad)
#define W1SP4  33

// shared memory layout (float offsets)
#define OFF_RS    0                     // 32 rows x 516       = 16512
#define OFF_W1S   16512                 // 32 x 132            = 4224
#define OFF_LF    20736                 // 512
#define OFF_LP    21248                 // 512
#define OFF_W2S   21760                 // 4 x 512             = 2048
#define OFF_GS    23808                 // 30 x 32             = 960
#define OFF_XB    24768                 // 32
#define OFF_CRED  24800                 // 32
#define OFF_LIN   24832                 // 32 x 4              = 128
#define OFF_EVD   24960                 // 128
#define OFF_AW    25088                 // 128
#define OFF_AW2   25216                 // 128
#define OFF_GG    25344                 // 30 x 8 -> 256
#define OFF_MK    25600                 // 32 ints
#define OFF_SC    25632                 // scalars
#define SMEM_FLOATS 25648

__global__ __launch_bounds__(256, 1)
void fused_attn_kernel(const float* __restrict__ left,
                       const float* __restrict__ right,
                       const int*   __restrict__ mask,
                       const float* __restrict__ W1,
                       const float* __restrict__ W2,
                       const float* __restrict__ W_o,
                       const float* __restrict__ b_o,
                       const float* __restrict__ scales_blk,
                       const float* __restrict__ W_c,
                       const float* __restrict__ b_c,
                       const float* __restrict__ scale_fin,
                       const float* __restrict__ W_aoa,
                       const float* __restrict__ b_aoa,
                       float* __restrict__ out)
{
    extern __shared__ float4 smem4[];
    float* sm   = (float*)smem4;
    float* rs   = sm + OFF_RS;
    float* w1s  = sm + OFF_W1S;
    float* lf   = sm + OFF_LF;
    float* lp   = sm + OFF_LP;
    float* w2s  = sm + OFF_W2S;
    float* gs   = sm + OFF_GS;
    float* xb   = sm + OFF_XB;
    float* credS= sm + OFF_CRED;
    float* linS = sm + OFF_LIN;
    float* evd  = sm + OFF_EVD;
    float* awS  = sm + OFF_AW;
    float* aw2S = sm + OFF_AW2;
    float* gg   = sm + OFF_GG;
    int*   mk   = (int*)(sm + OFF_MK);
    float* sc   = sm + OFF_SC;

    const int b    = blockIdx.x;
    const int t    = threadIdx.x;
    const int w    = t >> 5;
    const int lane = t & 31;

    // ------------------------------------------------------------------
    // Phase 0: load right tile, left vec, W2; init small buffers
    // ------------------------------------------------------------------
    {
        const float4* rg  = (const float4*)right + (size_t)b * (L_ * D_ / 4);
        float4* rs4 = (float4*)rs;
        for (int i = t; i < L_ * D_ / 4; i += 256) {
            int l = i >> 7, d4 = i & 127;
            rs4[l * RSP4 + d4] = rg[i];
        }
        // zero pad rows 30,31 (GEMM computes 32 l-rows)
        float4 z = make_float4(0.f, 0.f, 0.f, 0.f);
        {
            int l = 30 + (t >> 7), d4 = t & 127;
            rs4[l * RSP4 + d4] = z;
        }
        if (t < 128) ((float4*)lf)[t] = ((const float4*)left)[(size_t)b * 128 + t];
        for (int i = t; i < 512; i += 256) ((float4*)w2s)[i] = ((const float4*)W2)[i];
        if (t < L_) mk[t] = mask[b * L_ + t];
        if (t < 128) linS[t] = 0.f;
        if (t < 32) xb[t] = 1.f;
    }
    __syncthreads();
    if (t == 0) {
        int v = 0;
        for (int l = 0; l < L_; l++) v += mk[l];
        sc[0] = (float)v;
    }

    // ------------------------------------------------------------------
    // Phase 1: left projection lp[o] = left[b] . W1[o, 0:512]
    // warp-per-o with shuffle reduction
    // ------------------------------------------------------------------
    {
        const float4* lf4 = (const float4*)lf;
        for (int j = 0; j < 64; j++) {
            int o = w + 8 * j;
            const float4* wr = (const float4*)W1 + (size_t)o * 256;  // row = 1024 floats
            float a = 0.f;
            #pragma unroll
            for (int c = 0; c < 4; c++) {
                float4 wv = wr[c * 32 + lane];
                float4 lv = lf4[c * 32 + lane];
                a += wv.x * lv.x + wv.y * lv.y + wv.z * lv.z + wv.w * lv.w;
            }
            #pragma unroll
            for (int s = 16; s; s >>= 1) a += __shfl_xor_sync(0xffffffffu, a, s);
            if (lane == 0) lp[o] = a;
        }
    }

    // ------------------------------------------------------------------
    // Phase 2: Gram matrix G = right . right^T (symmetric, 465 pairs)
    // warp-per-pair
    // ------------------------------------------------------------------
    {
        const float4* rs4 = (const float4*)rs;
        for (int p = w; p < 465; p += 8) {
            int q = 0, rem = p;
            while (rem >= L_ - q) { rem -= L_ - q; q++; }
            int k = q + rem;
            const float4* r1 = rs4 + q * RSP4;
            const float4* r2 = rs4 + k * RSP4;
            float a = 0.f;
            #pragma unroll
            for (int c = 0; c < 4; c++) {
                float4 x = r1[c * 32 + lane];
                float4 y = r2[c * 32 + lane];
                a += x.x * y.x + x.y * y.y + x.z * y.z + x.w * y.w;
            }
            #pragma unroll
            for (int s = 16; s; s >>= 1) a += __shfl_xor_sync(0xffffffffu, a, s);
            if (lane == 0) { gs[q * 32 + k] = a; gs[k * 32 + q] = a; }
        }
    }
    __syncthreads();

    // ------------------------------------------------------------------
    // Phase 3: EvdCred iterations on G (tiny), then evd_cred
    // scores_i[q,k] = G[q,k] * Xb_{i-1}[k] * (inv_sqrt_d * scale_i)
    // ------------------------------------------------------------------
    const float inv_sqrt_d = 1.f / sqrtf((float)D_);
    for (int it = 0; it < ITER_; it++) {
        float nx = 0.f;
        if (t < L_) {
            float ci = inv_sqrt_d * scales_blk[it];
            float s = 0.f;
            for (int k = 0; k < L_; k++)
                if (mk[k]) s += gs[t * 32 + k] * xb[k];
            credS[t] = ci * s / sc[0];
        }
        __syncthreads();
        if (t < L_) {
            float y = b_o[it * L_ + t];
            const float* wo = W_o + it * L_ * L_ + t * L_;
            for (int q = 0; q < L_; q++) y += credS[q] * wo[q];
            nx = tanhf(expf(y));
        }
        __syncthreads();
        if (t < L_) xb[t] = nx;
        __syncthreads();
    }
    if (t < L_ * H_) {
        int l = t >> 2, h = t & 3;
        float cf = inv_sqrt_d * scale_fin[0];
        const float* wc = W_c + h * L_;
        float s = 0.f;
        for (int k = 0; k < L_; k++) s += gs[l * 32 + k] * xb[k] * wc[k];
        evd[t] = tanhf(expf(cf * s + b_c[h]));
    }
    // no sync needed yet; evd consumed after GEMM phase syncs

    // ------------------------------------------------------------------
    // Phase 4: big GEMM hidden = tanh(lp + right @ W1_right^T), fused W2:
    // lin[l][h] = sum_o W2[h][o] * hidden[l][o]
    // o-tiles of 32 (lane = o), warp handles 4 l-rows, K chunked by 128.
    // W1 tiles are register-prefetched one tile ahead so the LDG latency
    // overlaps the FMA body instead of sitting between the two barriers.
    // ------------------------------------------------------------------
    float linp[16];
    #pragma unroll
    for (int i = 0; i < 16; i++) linp[i] = 0.f;
    const int lb = w * 4;
    const float4* W14  = (const float4*)W1;
    float4*       w1s4 = (float4*)w1s;
    const float4* rs4c = (const float4*)rs;

    float4 pre0, pre1, pre2, pre3;
    {
        // prefetch tile (ot=0, kc=0)
        pre0 = W14[(size_t)(0 * 8 + w) * 256 + 128 + lane];
        pre1 = W14[(size_t)(1 * 8 + w) * 256 + 128 + lane];
        pre2 = W14[(size_t)(2 * 8 + w) * 256 + 128 + lane];
        pre3 = W14[(size_t)(3 * 8 + w) * 256 + 128 + lane];
    }

    for (int ot = 0; ot < 16; ot++) {
        const int o = ot * 32 + lane;
        float acc0 = 0.f, acc1 = 0.f, acc2 = 0.f, acc3 = 0.f;
        for (int kc = 0; kc < 4; kc++) {
            __syncthreads();
            // commit prefetched W1 tile to smem
            w1s4[(0 * 8 + w) * W1SP4 + lane] = pre0;
            w1s4[(1 * 8 + w) * W1SP4 + lane] = pre1;
            w1s4[(2 * 8 + w) * W1SP4 + lane] = pre2;
            w1s4[(3 * 8 + w) * W1SP4 + lane] = pre3;
            // issue prefetch of the NEXT tile (overlaps the compute below)
            int nt = ot * 4 + kc + 1;
            if (nt < 64) {
                int not_ = nt >> 2, nkc = nt & 3;
                size_t base = (size_t)(not_ * 32) * 256 + 128 + nkc * 32 + lane;
                pre0 = W14[base + (size_t)(0 * 8 + w) * 256];
                pre1 = W14[base + (size_t)(1 * 8 + w) * 256];
                pre2 = W14[base + (size_t)(2 * 8 + w) * 256];
                pre3 = W14[base + (size_t)(3 * 8 + w) * 256];
            }
            __syncthreads();
            const float4* rb = rs4c + lb * RSP4 + kc * 32;
            const float4* wb = (const float4*)w1s + lane * W1SP4;
            #pragma unroll 8
            for (int ks = 0; ks < 32; ks++) {
                float4 wv = wb[ks];
                float4 r0 = rb[ks];
                float4 r1 = rb[RSP4 + ks];
                float4 r2 = rb[2 * RSP4 + ks];
                float4 r3 = rb[3 * RSP4 + ks];
                acc0 += wv.x * r0.x + wv.y * r0.y + wv.z * r0.z + wv.w * r0.w;
                acc1 += wv.x * r1.x + wv.y * r1.y + wv.z * r1.z + wv.w * r1.w;
                acc2 += wv.x * r2.x + wv.y * r2.y + wv.z * r2.z + wv.w * r2.w;
                acc3 += wv.x * r3.x + wv.y * r3.y + wv.z * r3.z + wv.w * r3.w;
            }
        }
        // epilogue: tanh + W2 contraction into register partials
        float lpo = lp[o];
        float w20 = w2s[o], w21 = w2s[512 + o], w22 = w2s[1024 + o], w23 = w2s[1536 + o];
        float h0 = tanhf(lpo + acc0);
        float h1 = tanhf(lpo + acc1);
        float h2 = tanhf(lpo + acc2);
        float h3 = tanhf(lpo + acc3);
        linp[0]  += w20 * h0; linp[1]  += w21 * h0; linp[2]  += w22 * h0; linp[3]  += w23 * h0;
        linp[4]  += w20 * h1; linp[5]  += w21 * h1; linp[6]  += w22 * h1; linp[7]  += w23 * h1;
        linp[8]  += w20 * h2; linp[9]  += w21 * h2; linp[10] += w22 * h2; linp[11] += w23 * h2;
        linp[12] += w20 * h3; linp[13] += w21 * h3; linp[14] += w22 * h3; linp[15] += w23 * h3;
    }
    #pragma unroll
    for (int j = 0; j < 4; j++) {
        int l = lb + j;
        if (l < L_) {
            atomicAdd(&linS[l * 4 + 0], linp[j * 4 + 0]);
            atomicAdd(&linS[l * 4 + 1], linp[j * 4 + 1]);
            atomicAdd(&linS[l * 4 + 2], linp[j * 4 + 2]);
            atomicAdd(&linS[l * 4 + 3], linp[j * 4 + 3]);
        }
    }
    __syncthreads();

    // ------------------------------------------------------------------
    // Phase 5: masked softmax over l (per h)
    // ------------------------------------------------------------------
    if (t < H_) {
        int h = t;
        float m = -1e30f;
        for (int l = 0; l < L_; l++)
            if (mk[l]) m = fmaxf(m, linS[l * 4 + h]);
        float ssum = 0.f;
        for (int l = 0; l < L_; l++) {
            float e = mk[l] ? expf(linS[l * 4 + h] - m) : 0.f;
            awS[l * 4 + h] = e;
            ssum += e;
        }
        float inv = 1.f / ssum;
        for (int l = 0; l < L_; l++) awS[l * 4 + h] *= inv;
    }
    __syncthreads();

    // ------------------------------------------------------------------
    // Phase 6: AoA (GLU) fusion
    // ------------------------------------------------------------------
    if (t < L_ * 2 * H_) {          // 240
        int l = t >> 3, j = t & 7;
        float y = b_aoa[j];
        const float* wa = W_aoa + j * 8;
        #pragma unroll
        for (int m2 = 0; m2 < 8; m2++) {
            float c = (m2 < 4) ? awS[l * 4 + m2] : evd[l * 4 + (m2 - 4)];
            y += wa[m2] * c;
        }
        gg[l * 8 + j] = y;
    }
    __syncthreads();
    if (t < L_ * H_) {
        int l = t >> 2, h = t & 3;
        float a  = gg[l * 8 + h];
        float bb = gg[l * 8 + 4 + h];
        aw2S[l * 4 + h] = a / (1.f + expf(-bb));
    }
    __syncthreads();

    // ------------------------------------------------------------------
    // Phase 7: attended[b][d][h] = sum_l right[l][d] * aw2[l][h]
    // ------------------------------------------------------------------
    for (int d = t; d < 512; d += 256) {
        float a0 = 0.f, a1 = 0.f, a2 = 0.f, a3 = 0.f;
        for (int l = 0; l < L_; l++) {
            float r  = rs[l * RSP + d];
            float v0 = aw2S[l * 4 + 0];
            float v1 = aw2S[l * 4 + 1];
            float v2 = aw2S[l * 4 + 2];
            float v3 = aw2S[l * 4 + 3];
            a0 += r * v0; a1 += r * v1; a2 += r * v2; a3 += r * v3;
        }
        ((float4*)out)[(size_t)b * 512 + d] = make_float4(a0, a1, a2, a3);
    }

    // ------------------------------------------------------------------
    // Phase 8: second output = concat(evd_cred, aw2) per (b,l)
    // ------------------------------------------------------------------
    if (t < L_ * 2 * H_) {
        int l = t >> 3, j = t & 7;
        float v = (j < 4) ? evd[l * 4 + j] : aw2S[l * 4 + (j - 4)];
        out[(size_t)B_ * D_ * H_ + (size_t)b * (L_ * 2 * H_) + l * 8 + j] = v;
    }
}

extern "C" void kernel_launch(void* const* d_in, const int* in_sizes, int n_in,
                              void* d_out, int out_size)
{
    const float* left       = (const float*)d_in[0];
    const float* right      = (const float*)d_in[1];
    const int*   mask       = (const int*)  d_in[2];
    const float* W1         = (const float*)d_in[3];
    const float* W2         = (const float*)d_in[4];
    const float* W_o        = (const float*)d_in[5];
    const float* b_o        = (const float*)d_in[6];
    const float* scales_blk = (const float*)d_in[7];
    const float* W_c        = (const float*)d_in[8];
    const float* b_c        = (const float*)d_in[9];
    const float* scale_fin  = (const float*)d_in[10];
    const float* W_aoa      = (const float*)d_in[11];
    const float* b_aoa      = (const float*)d_in[12];
    float* out = (float*)d_out;

    size_t smem = SMEM_FLOATS * sizeof(float);
    cudaFuncSetAttribute(fused_attn_kernel,
                         cudaFuncAttributeMaxDynamicSharedMemorySize, (int)smem);
    fused_attn_kernel<<<B_, 256, smem>>>(left, right, mask, W1, W2, W_o, b_o,
                                         scales_blk, W_c, b_c, scale_fin,
                                         W_aoa, b_aoa, out);
}

// round 4
// speedup vs baseline: 1.0829x; 1.0829x over previous
#include <cuda_runtime.h>
#include <cstdint>
#include <math.h>

#define B_    2048
#define L_    30
#define D_    512
#define X_    512
#define H_    4
#define OUT_  512
#define ITER_ 4

#define RSP    516   // rs row stride in floats (512 + 4 pad)
#define RSP4   129   // in float4
#define KC     8     // K-chunk (floats) staged per cp.async stage
#define NSTAGE 64    // 512 / KC
#define WSROW4 3     // ws row pitch in float4 (2 data + 1 pad -> 48B, bank-clean)

// shared memory layout (float offsets)
#define OFF_RS    0                     // 32 x 516  = 16512
#define OFF_WS    16512                 // 512 x 12  = 6144  (ws: per-stage W1r chunk)
#define OFF_LF    22656                 // 512
#define OFF_LP    23168                 // 512
#define OFF_W2S   23680                 // 2048
#define OFF_GS    25728                 // 960
#define OFF_XB    26688                 // 32
#define OFF_CRED  26720                 // 32
#define OFF_LIN   26752                 // 128
#define OFF_EVD   26880                 // 128
#define OFF_AW    27008                 // 128
#define OFF_AW2   27136                 // 128
#define OFF_GG    27264                 // 256
#define OFF_MK    27520                 // 32 ints
#define OFF_SC    27552                 // 16
#define SMEM_FLOATS 27568               // 110272 bytes

__device__ __forceinline__ uint32_t s2u(const void* p) {
    return (uint32_t)__cvta_generic_to_shared(p);
}

__global__ __launch_bounds__(256, 2)
void fused_attn_kernel(const float* __restrict__ left,
                       const float* __restrict__ right,
                       const int*   __restrict__ mask,
                       const float* __restrict__ W1,
                       const float* __restrict__ W2,
                       const float* __restrict__ W_o,
                       const float* __restrict__ b_o,
                       const float* __restrict__ scales_blk,
                       const float* __restrict__ W_c,
                       const float* __restrict__ b_c,
                       const float* __restrict__ scale_fin,
                       const float* __restrict__ W_aoa,
                       const float* __restrict__ b_aoa,
                       float* __restrict__ out)
{
    extern __shared__ float4 smem4[];
    float* sm   = (float*)smem4;
    float* rs   = sm + OFF_RS;
    float* ws   = sm + OFF_WS;
    float* lf   = sm + OFF_LF;
    float* lp   = sm + OFF_LP;
    float* w2s  = sm + OFF_W2S;
    float* gs   = sm + OFF_GS;
    float* xb   = sm + OFF_XB;
    float* credS= sm + OFF_CRED;
    float* linS = sm + OFF_LIN;
    float* evd  = sm + OFF_EVD;
    float* awS  = sm + OFF_AW;
    float* aw2S = sm + OFF_AW2;
    float* gg   = sm + OFF_GG;
    int*   mk   = (int*)(sm + OFF_MK);
    float* sc   = sm + OFF_SC;

    const int b    = blockIdx.x;
    const int t    = threadIdx.x;
    const int w    = t >> 5;
    const int lane = t & 31;

    // ------------------------------------------------------------------
    // Phase 0: load right tile, left vec, W2; init small buffers
    // ------------------------------------------------------------------
    {
        const float4* rg  = (const float4*)right + (size_t)b * (L_ * D_ / 4);
        float4* rs4 = (float4*)rs;
        for (int i = t; i < L_ * D_ / 4; i += 256) {
            int l = i >> 7, d4 = i & 127;
            rs4[l * RSP4 + d4] = rg[i];
        }
        // zero pad rows 30,31 (GEMM computes 32 l-rows)
        {
            int l = 30 + (t >> 7), d4 = t & 127;
            rs4[l * RSP4 + d4] = make_float4(0.f, 0.f, 0.f, 0.f);
        }
        if (t < 128) ((float4*)lf)[t] = ((const float4*)left)[(size_t)b * 128 + t];
        for (int i = t; i < 512; i += 256) ((float4*)w2s)[i] = ((const float4*)W2)[i];
        if (t < L_) mk[t] = mask[b * L_ + t];
        if (t < 128) linS[t] = 0.f;
        if (t < 32) xb[t] = 1.f;
    }
    __syncthreads();
    if (t == 0) {
        int v = 0;
        for (int l = 0; l < L_; l++) v += mk[l];
        sc[0] = (float)v;
    }

    // ------------------------------------------------------------------
    // Phase 1: left projection lp[o] = left[b] . W1[o, 0:512]
    // ------------------------------------------------------------------
    {
        const float4* lf4 = (const float4*)lf;
        for (int j = 0; j < 64; j++) {
            int o = w + 8 * j;
            const float4* wr = (const float4*)W1 + (size_t)o * 256;  // row = 1024 floats
            float a = 0.f;
            #pragma unroll
            for (int c = 0; c < 4; c++) {
                float4 wv = wr[c * 32 + lane];
                float4 lv = lf4[c * 32 + lane];
                a += wv.x * lv.x + wv.y * lv.y + wv.z * lv.z + wv.w * lv.w;
            }
            #pragma unroll
            for (int s = 16; s; s >>= 1) a += __shfl_xor_sync(0xffffffffu, a, s);
            if (lane == 0) lp[o] = a;
        }
    }

    // ------------------------------------------------------------------
    // Phase 2: Gram matrix G = right . right^T (symmetric, 465 pairs)
    // ------------------------------------------------------------------
    {
        const float4* rs4 = (const float4*)rs;
        for (int p = w; p < 465; p += 8) {
            int q = 0, rem = p;
            while (rem >= L_ - q) { rem -= L_ - q; q++; }
            int k = q + rem;
            const float4* r1 = rs4 + q * RSP4;
            const float4* r2 = rs4 + k * RSP4;
            float a = 0.f;
            #pragma unroll
            for (int c = 0; c < 4; c++) {
                float4 x = r1[c * 32 + lane];
                float4 y = r2[c * 32 + lane];
                a += x.x * y.x + x.y * y.y + x.z * y.z + x.w * y.w;
            }
            #pragma unroll
            for (int s = 16; s; s >>= 1) a += __shfl_xor_sync(0xffffffffu, a, s);
            if (lane == 0) { gs[q * 32 + k] = a; gs[k * 32 + q] = a; }
        }
    }
    __syncthreads();

    // ------------------------------------------------------------------
    // Phase 3: EvdCred iterations on G, then evd_cred
    // ------------------------------------------------------------------
    const float inv_sqrt_d = 1.f / sqrtf((float)D_);
    for (int it = 0; it < ITER_; it++) {
        float nx = 0.f;
        if (t < L_) {
            float ci = inv_sqrt_d * scales_blk[it];
            float s = 0.f;
            for (int k = 0; k < L_; k++)
                if (mk[k]) s += gs[t * 32 + k] * xb[k];
            credS[t] = ci * s / sc[0];
        }
        __syncthreads();
        if (t < L_) {
            float y = b_o[it * L_ + t];
            const float* wo_ = W_o + it * L_ * L_ + t * L_;
            for (int q = 0; q < L_; q++) y += credS[q] * wo_[q];
            nx = tanhf(expf(y));
        }
        __syncthreads();
        if (t < L_) xb[t] = nx;
        __syncthreads();
    }
    if (t < L_ * H_) {
        int l = t >> 2, h = t & 3;
        float cf = inv_sqrt_d * scale_fin[0];
        const float* wc = W_c + h * L_;
        float s = 0.f;
        for (int k = 0; k < L_; k++) s += gs[l * 32 + k] * xb[k] * wc[k];
        evd[t] = tanhf(expf(cf * s + b_c[h]));
    }
    // evd consumed in Phase 6, after multiple barriers

    // ------------------------------------------------------------------
    // Phase 4: big GEMM hidden = tanh(lp + right @ W1r^T), fused W2.
    // Register tile 8l x 8o per thread:
    //   wl = w>>1 -> l rows wl*8..wl*8+7
    //   wo = w&1  -> o set  wo*256 + jj*32 + lane  (jj = 0..7)
    // W1r streamed in K-chunks of 8 via cp.async into ws
    // (row pitch 48B -> lane-stride 48B covers all 8 bank slots, conflict-free).
    // ------------------------------------------------------------------
    const int wl = w >> 1;
    const int wo = w & 1;

    float acc[8][8];
    #pragma unroll
    for (int i = 0; i < 8; i++)
        #pragma unroll
        for (int jj = 0; jj < 8; jj++) acc[i][jj] = 0.f;

    const float4* rs4c = (const float4*)rs;
    float4*       ws4  = (float4*)ws;

    for (int kc = 0; kc < NSTAGE; kc++) {
        __syncthreads();   // prior compute done before overwrite
        // stage W1r[0:512][kc*8 .. kc*8+7] : 1024 float4 items, 4 per thread
        #pragma unroll
        for (int it = 0; it < 4; it++) {
            int item = it * 256 + t;
            int o    = item >> 1;
            int kk4  = item & 1;
            const float* gsrc = W1 + (size_t)o * 1024 + 512 + kc * KC + kk4 * 4;
            uint32_t sdst = s2u(&ws4[o * WSROW4 + kk4]);
            asm volatile("cp.async.ca.shared.global [%0], [%1], 16;"
                         :: "r"(sdst), "l"(gsrc));
        }
        asm volatile("cp.async.commit_group;");
        asm volatile("cp.async.wait_group 0;" ::: "memory");
        __syncthreads();   // chunk visible to all warps

        #pragma unroll
        for (int kk4 = 0; kk4 < 2; kk4++) {
            float4 wf[8];
            #pragma unroll
            for (int jj = 0; jj < 8; jj++)
                wf[jj] = ws4[(wo * 256 + jj * 32 + lane) * WSROW4 + kk4];
            const float4* rb = rs4c + (wl * 8) * RSP4 + kc * 2 + kk4;
            #pragma unroll
            for (int i = 0; i < 8; i++) {
                float4 rv = rb[i * RSP4];   // warp-uniform broadcast
                #pragma unroll
                for (int jj = 0; jj < 8; jj++) {
                    acc[i][jj] += rv.x * wf[jj].x + rv.y * wf[jj].y
                                + rv.z * wf[jj].z + rv.w * wf[jj].w;
                }
            }
        }
    }

    // epilogue: tanh + W2 contraction, warp-reduce over lanes, atomics from lane 0
    {
        float lpv[8];
        #pragma unroll
        for (int jj = 0; jj < 8; jj++) lpv[jj] = lp[wo * 256 + jj * 32 + lane];
        #pragma unroll
        for (int i = 0; i < 8; i++) {
            float hv[8];
            #pragma unroll
            for (int jj = 0; jj < 8; jj++) hv[jj] = tanhf(lpv[jj] + acc[i][jj]);
            int l = wl * 8 + i;
            #pragma unroll
            for (int h = 0; h < 4; h++) {
                float p = 0.f;
                #pragma unroll
                for (int jj = 0; jj < 8; jj++)
                    p += w2s[h * 512 + wo * 256 + jj * 32 + lane] * hv[jj];
                #pragma unroll
                for (int s = 16; s; s >>= 1) p += __shfl_xor_sync(0xffffffffu, p, s);
                if (lane == 0 && l < L_) atomicAdd(&linS[l * 4 + h], p);
            }
        }
    }
    __syncthreads();

    // ------------------------------------------------------------------
    // Phase 5: masked softmax over l (per h)
    // ------------------------------------------------------------------
    if (t < H_) {
        int h = t;
        float m = -1e30f;
        for (int l = 0; l < L_; l++)
            if (mk[l]) m = fmaxf(m, linS[l * 4 + h]);
        float ssum = 0.f;
        for (int l = 0; l < L_; l++) {
            float e = mk[l] ? expf(linS[l * 4 + h] - m) : 0.f;
            awS[l * 4 + h] = e;
            ssum += e;
        }
        float inv = 1.f / ssum;
        for (int l = 0; l < L_; l++) awS[l * 4 + h] *= inv;
    }
    __syncthreads();

    // ------------------------------------------------------------------
    // Phase 6: AoA (GLU) fusion
    // ------------------------------------------------------------------
    if (t < L_ * 2 * H_) {          // 240
        int l = t >> 3, j = t & 7;
        float y = b_aoa[j];
        const float* wa = W_aoa + j * 8;
        #pragma unroll
        for (int m2 = 0; m2 < 8; m2++) {
            float c = (m2 < 4) ? awS[l * 4 + m2] : evd[l * 4 + (m2 - 4)];
            y += wa[m2] * c;
        }
        gg[l * 8 + j] = y;
    }
    __syncthreads();
    if (t < L_ * H_) {
        int l = t >> 2, h = t & 3;
        float a  = gg[l * 8 + h];
        float bb = gg[l * 8 + 4 + h];
        aw2S[l * 4 + h] = a / (1.f + expf(-bb));
    }
    __syncthreads();

    // ------------------------------------------------------------------
    // Phase 7: attended[b][d][h] = sum_l right[l][d] * aw2[l][h]
    // ------------------------------------------------------------------
    for (int d = t; d < 512; d += 256) {
        float a0 = 0.f, a1 = 0.f, a2 = 0.f, a3 = 0.f;
        for (int l = 0; l < L_; l++) {
            float r  = rs[l * RSP + d];
            a0 += r * aw2S[l * 4 + 0];
            a1 += r * aw2S[l * 4 + 1];
            a2 += r * aw2S[l * 4 + 2];
            a3 += r * aw2S[l * 4 + 3];
        }
        ((float4*)out)[(size_t)b * 512 + d] = make_float4(a0, a1, a2, a3);
    }

    // ------------------------------------------------------------------
    // Phase 8: second output = concat(evd_cred, aw2) per (b,l)
    // ------------------------------------------------------------------
    if (t < L_ * 2 * H_) {
        int l = t >> 3, j = t & 7;
        float v = (j < 4) ? evd[l * 4 + j] : aw2S[l * 4 + (j - 4)];
        out[(size_t)B_ * D_ * H_ + (size_t)b * (L_ * 2 * H_) + l * 8 + j] = v;
    }
}

extern "C" void kernel_launch(void* const* d_in, const int* in_sizes, int n_in,
                              void* d_out, int out_size)
{
    const float* left       = (const float*)d_in[0];
    const float* right      = (const float*)d_in[1];
    const int*   mask       = (const int*)  d_in[2];
    const float* W1         = (const float*)d_in[3];
    const float* W2         = (const float*)d_in[4];
    const float* W_o        = (const float*)d_in[5];
    const float* b_o        = (const float*)d_in[6];
    const float* scales_blk = (const float*)d_in[7];
    const float* W_c        = (const float*)d_in[8];
    const float* b_c        = (const float*)d_in[9];
    const float* scale_fin  = (const float*)d_in[10];
    const float* W_aoa      = (const float*)d_in[11];
    const float* b_aoa      = (const float*)d_in[12];
    float* out = (float*)d_out;

    size_t smem = SMEM_FLOATS * sizeof(float);
    cudaFuncSetAttribute(fused_attn_kernel,
                         cudaFuncAttributeMaxDynamicSharedMemorySize, (int)smem);
    fused_attn_kernel<<<B_, 256, smem>>>(left, right, mask, W1, W2, W_o, b_o,
                                         scales_blk, W_c, b_c, scale_fin,
                                         W_aoa, b_aoa, out);
}

// round 7
// speedup vs baseline: 1.8685x; 1.7254x over previous
#include <cuda_runtime.h>
#include <cuda_bf16.h>
#include <cstdint>
#include <math.h>

#define B_    2048
#define L_    30
#define D_    512
#define X_    512
#define H_    4
#define OUT_  512
#define ITER_ 4

// GEMM tiling: per CTA 4 batches -> M=128, N=512 (4 passes of 128), K=512 (4 chunks of 128)
#define TP    136            // tile pitch in bf16 elems (272B: +4 bank shift per row)
#define TILE_B (128 * TP * 2)   // 34816 bytes per tile

#define SOFF_AH  0
#define SOFF_AL  (TILE_B)
#define SOFF_BH  (2 * TILE_B)
#define SOFF_BL  (3 * TILE_B)
#define SOFF_MISC (4 * TILE_B)   // 139264

// misc float offsets (from SOFF_MISC)
#define FOFF_LF    0        // 4x512
#define FOFF_LP    2048     // 4x512
#define FOFF_W2S   4096     // 2048
#define FOFF_GS    6144     // 4x900
#define FOFF_XB    9744     // 128
#define FOFF_CRED  9872     // 128
#define FOFF_LIN   10000    // 512
#define FOFF_EVD   10512    // 512
#define FOFF_AW    11024    // 512
#define FOFF_AW2   11536    // 512
#define FOFF_GG    12048    // 960
#define FOFF_MK    13008    // 128 ints
#define FOFF_SC    13136    // 8
#define MISC_FLOATS 13144
#define SMEM_BYTES (SOFF_MISC + MISC_FLOATS * 4)   // 191840

__device__ __align__(16) __nv_bfloat16 g_W1h[OUT_ * 1024];
__device__ __align__(16) __nv_bfloat16 g_W1l[OUT_ * 1024];

__device__ __forceinline__ uint32_t s2u(const void* p) {
    return (uint32_t)__cvta_generic_to_shared(p);
}
__device__ __forceinline__ void cvt2(float a, float b, uint32_t& hi, uint32_t& lo) {
    __nv_bfloat162 h = __floats2bfloat162_rn(a, b);
    float ra = a - __bfloat162float(h.x);
    float rb = b - __bfloat162float(h.y);
    __nv_bfloat162 l = __floats2bfloat162_rn(ra, rb);
    hi = *(uint32_t*)&h;
    lo = *(uint32_t*)&l;
}
__device__ __forceinline__ void ldm4(uint32_t* r, uint32_t addr) {
    asm volatile("ldmatrix.sync.aligned.m8n8.x4.shared.b16 {%0,%1,%2,%3}, [%4];"
        : "=r"(r[0]), "=r"(r[1]), "=r"(r[2]), "=r"(r[3]) : "r"(addr));
}
__device__ __forceinline__ void mma16816(float* c, const uint32_t* a, const uint32_t* b) {
    asm volatile("mma.sync.aligned.m16n8k16.row.col.f32.bf16.bf16.f32 "
        "{%0,%1,%2,%3}, {%4,%5,%6,%7}, {%8,%9}, {%0,%1,%2,%3};"
        : "+f"(c[0]), "+f"(c[1]), "+f"(c[2]), "+f"(c[3])
        : "r"(a[0]), "r"(a[1]), "r"(a[2]), "r"(a[3]), "r"(b[0]), "r"(b[1]));
}

__global__ void convert_w1_kernel(const float* __restrict__ W1) {
    int i = blockIdx.x * blockDim.x + threadIdx.x;   // 524288 = 512*1024
    float x = W1[i];
    __nv_bfloat16 h = __float2bfloat16(x);
    g_W1h[i] = h;
    g_W1l[i] = __float2bfloat16(x - __bfloat162float(h));
}

__global__ __launch_bounds__(256, 1)
void fused_attn_mma_kernel(const float* __restrict__ left,
                           const float* __restrict__ right,
                           const int*   __restrict__ mask,
                           const float* __restrict__ W1,
                           const float* __restrict__ W2,
                           const float* __restrict__ W_o,
                           const float* __restrict__ b_o,
                           const float* __restrict__ scales_blk,
                           const float* __restrict__ W_c,
                           const float* __restrict__ b_c,
                           const float* __restrict__ scale_fin,
                           const float* __restrict__ W_aoa,
                           const float* __restrict__ b_aoa,
                           float* __restrict__ out)
{
    extern __shared__ char smemc[];
    char*  Ah   = smemc + SOFF_AH;
    char*  Al   = smemc + SOFF_AL;
    char*  Bh   = smemc + SOFF_BH;
    char*  Bl   = smemc + SOFF_BL;
    float* mf   = (float*)(smemc + SOFF_MISC);
    float* lf   = mf + FOFF_LF;
    float* lp   = mf + FOFF_LP;
    float* w2s  = mf + FOFF_W2S;
    float* gs   = mf + FOFF_GS;
    float* xb   = mf + FOFF_XB;
    float* cred = mf + FOFF_CRED;
    float* linS = mf + FOFF_LIN;
    float* evdS = mf + FOFF_EVD;
    float* awS  = mf + FOFF_AW;
    float* aw2S = mf + FOFF_AW2;
    float* gg   = mf + FOFF_GG;
    int*   mk   = (int*)(mf + FOFF_MK);
    float* sc   = mf + FOFF_SC;

    const int b4   = blockIdx.x * 4;
    const int t    = threadIdx.x;
    const int w    = t >> 5;
    const int lane = t & 31;

    // ---------------- Phase 0: misc loads ----------------
    {
        const float4* lsrc = (const float4*)(left + (size_t)b4 * X_);
        ((float4*)lf)[t]       = lsrc[t];
        ((float4*)lf)[t + 256] = lsrc[t + 256];
        ((float4*)w2s)[t]       = ((const float4*)W2)[t];
        ((float4*)w2s)[t + 256] = ((const float4*)W2)[t + 256];
        if (t < 120) {
            int bb = t / 30, l = t % 30;
            mk[bb * 32 + l] = mask[(b4 + bb) * L_ + l];
        }
        for (int i = t; i < 512; i += 256) linS[i] = 0.f;
        if (t < 128) xb[t] = 1.f;
    }
    __syncthreads();
    if (t < 4) {
        int v = 0;
        for (int l = 0; l < L_; l++) v += mk[t * 32 + l];
        sc[t] = (float)v;
    }

    // ---------------- Phase 1: lp[bb][o] = left[bb] . W1[o, 0:512] ----------------
    {
        const float4* W14 = (const float4*)W1;
        const float4* lf4 = (const float4*)lf;
        for (int j = 0; j < 64; j++) {
            int o = w + 8 * j;
            float a0 = 0.f, a1 = 0.f, a2 = 0.f, a3 = 0.f;
            #pragma unroll
            for (int c = 0; c < 4; c++) {
                float4 wv = W14[(size_t)o * 256 + c * 32 + lane];
                float4 l0 = lf4[0 * 128 + c * 32 + lane];
                float4 l1 = lf4[1 * 128 + c * 32 + lane];
                float4 l2 = lf4[2 * 128 + c * 32 + lane];
                float4 l3 = lf4[3 * 128 + c * 32 + lane];
                a0 += wv.x * l0.x + wv.y * l0.y + wv.z * l0.z + wv.w * l0.w;
                a1 += wv.x * l1.x + wv.y * l1.y + wv.z * l1.z + wv.w * l1.w;
                a2 += wv.x * l2.x + wv.y * l2.y + wv.z * l2.z + wv.w * l2.w;
                a3 += wv.x * l3.x + wv.y * l3.y + wv.z * l3.z + wv.w * l3.w;
            }
            #pragma unroll
            for (int s = 16; s; s >>= 1) {
                a0 += __shfl_xor_sync(0xffffffffu, a0, s);
                a1 += __shfl_xor_sync(0xffffffffu, a1, s);
                a2 += __shfl_xor_sync(0xffffffffu, a2, s);
                a3 += __shfl_xor_sync(0xffffffffu, a3, s);
            }
            if (lane == 0) {
                lp[0 * 512 + o] = a0; lp[1 * 512 + o] = a1;
                lp[2 * 512 + o] = a2; lp[3 * 512 + o] = a3;
            }
        }
    }

    // ---------------- Phase 2: Gram matrices (4 batches) ----------------
    for (int bb = 0; bb < 4; bb++) {
        const float4* rbase = (const float4*)(right + (size_t)(b4 + bb) * L_ * D_);
        float* gsb = gs + bb * 900;
        for (int p = w; p < 465; p += 8) {
            int q = 0, rem = p;
            while (rem >= L_ - q) { rem -= L_ - q; q++; }
            int k2 = q + rem;
            const float4* r1 = rbase + q  * 128;
            const float4* r2 = rbase + k2 * 128;
            float a = 0.f;
            #pragma unroll
            for (int c = 0; c < 4; c++) {
                float4 x = r1[c * 32 + lane];
                float4 y = r2[c * 32 + lane];
                a += x.x * y.x + x.y * y.y + x.z * y.z + x.w * y.w;
            }
            #pragma unroll
            for (int s = 16; s; s >>= 1) a += __shfl_xor_sync(0xffffffffu, a, s);
            if (lane == 0) { gsb[q * 30 + k2] = a; gsb[k2 * 30 + q] = a; }
        }
    }
    __syncthreads();

    // ---------------- Phase 3: EvdCred + evd ----------------
    const float inv_sqrt_d = 1.f / sqrtf((float)D_);
    {
        int bb = t >> 5, l = t & 31;
        bool act = (t < 128) && (l < 30);
        for (int it = 0; it < ITER_; it++) {
            float nx = 0.f;
            if (act) {
                float ci = inv_sqrt_d * scales_blk[it];
                float s = 0.f;
                const float* gsb = gs + bb * 900 + l * 30;
                for (int k = 0; k < L_; k++)
                    if (mk[bb * 32 + k]) s += gsb[k] * xb[bb * 32 + k];
                cred[bb * 32 + l] = ci * s / sc[bb];
            }
            __syncthreads();
            if (act) {
                float y = b_o[it * L_ + l];
                const float* wo_ = W_o + it * L_ * L_ + l * L_;
                for (int q = 0; q < L_; q++) y += cred[bb * 32 + q] * wo_[q];
                nx = tanhf(expf(y));
            }
            __syncthreads();
            if (act) xb[bb * 32 + l] = nx;
            __syncthreads();
        }
    }
    for (int idx = t; idx < 480; idx += 256) {
        int bb = idx / 120, rem = idx % 120;
        int l = rem >> 2, h = rem & 3;
        float cf = inv_sqrt_d * scale_fin[0];
        const float* wc = W_c + h * L_;
        const float* gsb = gs + bb * 900 + l * 30;
        float s = 0.f;
        for (int k = 0; k < L_; k++) s += gsb[k] * xb[bb * 32 + k] * wc[k];
        evdS[bb * 128 + l * 4 + h] = tanhf(expf(cf * s + b_c[h]));
    }

    // ---------------- Phase 4: tensor GEMM (bf16 3-term split, mma.sync) ----------------
    const int wm = w & 3;      // M quarter (rows wm*32..+31)
    const int wn = w >> 2;     // N half   (cols wn*64..+63)
    // ldmatrix lane address components
    const int mi   = lane >> 3;
    const int rA0  = wm * 32 + (mi & 1) * 8 + (lane & 7);   // + mi2*16
    const int kAo  = (mi >> 1) * 8;
    const int rB0  = wn * 64 + (lane >> 4) * 8 + (lane & 7); // + pair*16
    const int kBo  = (mi & 1) * 8;
    const uint32_t uAh = s2u(Ah), uAl = s2u(Al), uBh = s2u(Bh), uBl = s2u(Bl);

    float linp[4][4];
    #pragma unroll
    for (int i = 0; i < 4; i++)
        #pragma unroll
        for (int h = 0; h < 4; h++) linp[i][h] = 0.f;

    const int g    = lane >> 2;
    const int ncol = (lane & 3) * 2;

    for (int nh = 0; nh < 4; nh++) {
        float acc[2][8][4];
        #pragma unroll
        for (int i = 0; i < 2; i++)
            #pragma unroll
            for (int j = 0; j < 8; j++)
                #pragma unroll
                for (int c = 0; c < 4; c++) acc[i][j][c] = 0.f;

        for (int kc = 0; kc < 4; kc++) {
            __syncthreads();   // previous mma reads done
            // ---- stage A (convert fp32 -> bf16 hi/lo) ----
            {
                int m = t >> 1, half = t & 1;
                int bb = m >> 5, l = m & 31;
                bool val = (l < 30);
                const float4* src4 = (const float4*)(right +
                    ((size_t)(b4 + bb) * L_ + l) * D_ + kc * 128 + half * 64);
                uint32_t dstb = (uint32_t)(m * (TP * 2) + half * 128);
                #pragma unroll
                for (int j = 0; j < 8; j++) {
                    float4 x0 = val ? src4[2 * j]     : make_float4(0.f, 0.f, 0.f, 0.f);
                    float4 x1 = val ? src4[2 * j + 1] : make_float4(0.f, 0.f, 0.f, 0.f);
                    uint4 hv, lv;
                    cvt2(x0.x, x0.y, hv.x, lv.x);
                    cvt2(x0.z, x0.w, hv.y, lv.y);
                    cvt2(x1.x, x1.y, hv.z, lv.z);
                    cvt2(x1.z, x1.w, hv.w, lv.w);
                    *(uint4*)(Ah + dstb + j * 16) = hv;
                    *(uint4*)(Al + dstb + j * 16) = lv;
                }
            }
            // ---- stage B (preconverted bf16 hi/lo, cp.async) ----
            {
                int r = t >> 1, half = t & 1;
                size_t eoff = (size_t)(nh * 128 + r) * 1024 + 512 + kc * 128 + half * 64;
                uint32_t dstb = (uint32_t)(r * (TP * 2) + half * 128);
                #pragma unroll
                for (int j = 0; j < 8; j++) {
                    asm volatile("cp.async.ca.shared.global [%0], [%1], 16;"
                        :: "r"(uBh + dstb + j * 16), "l"(g_W1h + eoff + j * 8));
                    asm volatile("cp.async.ca.shared.global [%0], [%1], 16;"
                        :: "r"(uBl + dstb + j * 16), "l"(g_W1l + eoff + j * 8));
                }
                asm volatile("cp.async.commit_group;");
                asm volatile("cp.async.wait_group 0;" ::: "memory");
            }
            __syncthreads();

            // ---- mma over 8 k16 steps ----
            #pragma unroll
            for (int ks = 0; ks < 8; ks++) {
                uint32_t ah[2][4], al[2][4], bh[4][4], bl[4][4];
                #pragma unroll
                for (int mi2 = 0; mi2 < 2; mi2++) {
                    uint32_t off = (uint32_t)((rA0 + mi2 * 16) * TP + ks * 16 + kAo) * 2;
                    ldm4(ah[mi2], uAh + off);
                    ldm4(al[mi2], uAl + off);
                }
                #pragma unroll
                for (int pr = 0; pr < 4; pr++) {
                    uint32_t off = (uint32_t)((rB0 + pr * 16) * TP + ks * 16 + kBo) * 2;
                    ldm4(bh[pr], uBh + off);
                    ldm4(bl[pr], uBl + off);
                }
                #pragma unroll
                for (int mi2 = 0; mi2 < 2; mi2++) {
                    #pragma unroll
                    for (int pr = 0; pr < 4; pr++) {
                        mma16816(acc[mi2][pr * 2],     ah[mi2], &bh[pr][0]);
                        mma16816(acc[mi2][pr * 2 + 1], ah[mi2], &bh[pr][2]);
                        mma16816(acc[mi2][pr * 2],     ah[mi2], &bl[pr][0]);
                        mma16816(acc[mi2][pr * 2 + 1], ah[mi2], &bl[pr][2]);
                        mma16816(acc[mi2][pr * 2],     al[mi2], &bh[pr][0]);
                        mma16816(acc[mi2][pr * 2 + 1], al[mi2], &bh[pr][2]);
                    }
                }
            }
        }

        // ---- epilogue for this nh: tanh + W2 contraction into linp ----
        #pragma unroll
        for (int mi2 = 0; mi2 < 2; mi2++) {
            #pragma unroll
            for (int ni = 0; ni < 8; ni++) {
                #pragma unroll
                for (int c = 0; c < 4; c++) {
                    int row = wm * 32 + mi2 * 16 + g + (c >> 1) * 8;
                    int l = row & 31;
                    if (l < 30) {
                        int bb = row >> 5;
                        int o = nh * 128 + wn * 64 + ni * 8 + ncol + (c & 1);
                        float hv = tanhf(lp[bb * 512 + o] + acc[mi2][ni][c]);
                        int ridx = mi2 * 2 + (c >> 1);
                        linp[ridx][0] += w2s[o] * hv;
                        linp[ridx][1] += w2s[512 + o] * hv;
                        linp[ridx][2] += w2s[1024 + o] * hv;
                        linp[ridx][3] += w2s[1536 + o] * hv;
                    }
                }
            }
        }
    }

    // reduce linp over the 4 lanes sharing each row, then atomics
    #pragma unroll
    for (int ridx = 0; ridx < 4; ridx++) {
        #pragma unroll
        for (int h = 0; h < 4; h++) {
            float p = linp[ridx][h];
            p += __shfl_xor_sync(0xffffffffu, p, 1);
            p += __shfl_xor_sync(0xffffffffu, p, 2);
            if ((lane & 3) == 0) {
                int row = wm * 32 + (ridx >> 1) * 16 + g + (ridx & 1) * 8;
                if ((row & 31) < 30) atomicAdd(&linS[row * 4 + h], p);
            }
        }
    }
    __syncthreads();

    // ---------------- Phase 5: masked softmax ----------------
    if (t < 16) {
        int bb = t >> 2, h = t & 3;
        float m = -1e30f;
        for (int l = 0; l < L_; l++)
            if (mk[bb * 32 + l]) m = fmaxf(m, linS[(bb * 32 + l) * 4 + h]);
        float ssum = 0.f;
        for (int l = 0; l < L_; l++) {
            float e = mk[bb * 32 + l] ? expf(linS[(bb * 32 + l) * 4 + h] - m) : 0.f;
            awS[bb * 128 + l * 4 + h] = e;
            ssum += e;
        }
        float inv = 1.f / ssum;
        for (int l = 0; l < L_; l++) awS[bb * 128 + l * 4 + h] *= inv;
    }
    __syncthreads();

    // ---------------- Phase 6: AoA (GLU) ----------------
    for (int idx = t; idx < 960; idx += 256) {
        int bb = idx / 240, rem = idx % 240;
        int l = rem >> 3, j = rem & 7;
        float y = b_aoa[j];
        const float* wa = W_aoa + j * 8;
        #pragma unroll
        for (int m2 = 0; m2 < 8; m2++) {
            float c = (m2 < 4) ? awS[bb * 128 + l * 4 + m2]
                               : evdS[bb * 128 + l * 4 + (m2 - 4)];
            y += wa[m2] * c;
        }
        gg[bb * 240 + l * 8 + j] = y;
    }
    __syncthreads();
    for (int idx = t; idx < 480; idx += 256) {
        int bb = idx / 120, rem = idx % 120;
        int l = rem >> 2, h = rem & 3;
        float a  = gg[bb * 240 + l * 8 + h];
        float bv = gg[bb * 240 + l * 8 + 4 + h];
        aw2S[bb * 128 + l * 4 + h] = a / (1.f + expf(-bv));
    }
    __syncthreads();

    // ---------------- Phase 7: attended ----------------
    for (int bb = 0; bb < 4; bb++) {
        const float* rb = right + (size_t)(b4 + bb) * L_ * D_;
        for (int d = t; d < 512; d += 256) {
            float a0 = 0.f, a1 = 0.f, a2 = 0.f, a3 = 0.f;
            for (int l = 0; l < L_; l++) {
                float r = rb[l * D_ + d];
                a0 += r * aw2S[bb * 128 + l * 4 + 0];
                a1 += r * aw2S[bb * 128 + l * 4 + 1];
                a2 += r * aw2S[bb * 128 + l * 4 + 2];
                a3 += r * aw2S[bb * 128 + l * 4 + 3];
            }
            ((float4*)out)[(size_t)(b4 + bb) * 512 + d] = make_float4(a0, a1, a2, a3);
        }
    }

    // ---------------- Phase 8: second output ----------------
    for (int idx = t; idx < 960; idx += 256) {
        int bb = idx / 240, rem = idx % 240;
        int l = rem >> 3, j = rem & 7;
        float v = (j < 4) ? evdS[bb * 128 + l * 4 + j]
                          : aw2S[bb * 128 + l * 4 + (j - 4)];
        out[(size_t)B_ * D_ * H_ + (size_t)(b4 + bb) * (L_ * 2 * H_) + l * 8 + j] = v;
    }
}

extern "C" void kernel_launch(void* const* d_in, const int* in_sizes, int n_in,
                              void* d_out, int out_size)
{
    const float* left       = (const float*)d_in[0];
    const float* right      = (const float*)d_in[1];
    const int*   mask       = (const int*)  d_in[2];
    const float* W1         = (const float*)d_in[3];
    const float* W2         = (const float*)d_in[4];
    const float* W_o        = (const float*)d_in[5];
    const float* b_o        = (const float*)d_in[6];
    const float* scales_blk = (const float*)d_in[7];
    const float* W_c        = (const float*)d_in[8];
    const float* b_c        = (const float*)d_in[9];
    const float* scale_fin  = (const float*)d_in[10];
    const float* W_aoa      = (const float*)d_in[11];
    const float* b_aoa      = (const float*)d_in[12];
    float* out = (float*)d_out;

    convert_w1_kernel<<<2048, 256>>>(W1);

    cudaFuncSetAttribute(fused_attn_mma_kernel,
                         cudaFuncAttributeMaxDynamicSharedMemorySize, SMEM_BYTES);
    fused_attn_mma_kernel<<<B_ / 4, 256, SMEM_BYTES>>>(left, right, mask, W1, W2,
                                                       W_o, b_o, scales_blk, W_c,
                                                       b_c, scale_fin, W_aoa, b_aoa,
                                                       out);
}

// round 9
// speedup vs baseline: 2.8106x; 1.5042x over previous
#include <cuda_runtime.h>
#include <cuda_bf16.h>
#include <cstdint>
#include <math.h>

#define B_    2048
#define L_    30
#define D_    512
#define X_    512
#define H_    4
#define OUT_  512
#define ITER_ 4

#define THREADS 512
// tiles: 128 rows x 64 bf16 cols (128B/row), XOR swizzle (chunk ^ (row&7))
#define TILE    16384
#define STAGEB  65536          // Ah,Al,Bh,Bl per stage
#define SOFF_MISC 131072       // 2 stages of tiles before this

// misc float offsets
#define FOFF_LP   0            // 4 x 512
#define FOFF_W2S  2048         // 2048
#define FOFF_GS   4096         // 4 x 900
#define FOFF_XB   7696         // 128
#define FOFF_CRED 7824         // 128
#define FOFF_LIN  7952         // 512
#define FOFF_EVD  8464         // 512
#define FOFF_AW   8976         // 512
#define FOFF_AW2  9488         // 512
#define FOFF_GG   10000        // 960
#define FOFF_MK   10960        // 128 ints
#define FOFF_SC   11088        // 8
#define MISC_FLOATS 11096
#define SMEM_BYTES (SOFF_MISC + MISC_FLOATS * 4)   // 175456

// preconverted operands (bf16 hi/lo)
__device__ __align__(16) __nv_bfloat16 g_W1h[OUT_ * 1024];
__device__ __align__(16) __nv_bfloat16 g_W1l[OUT_ * 1024];
__device__ __align__(16) __nv_bfloat16 g_rh[(size_t)B_ * 32 * D_];
__device__ __align__(16) __nv_bfloat16 g_rl[(size_t)B_ * 32 * D_];

__device__ __forceinline__ uint32_t s2u(const void* p) {
    return (uint32_t)__cvta_generic_to_shared(p);
}
__device__ __forceinline__ void cvt2(float a, float b, uint32_t& hi, uint32_t& lo) {
    __nv_bfloat162 h = __floats2bfloat162_rn(a, b);
    float ra = a - __bfloat162float(h.x);
    float rb = b - __bfloat162float(h.y);
    __nv_bfloat162 l = __floats2bfloat162_rn(ra, rb);
    hi = *(uint32_t*)&h;
    lo = *(uint32_t*)&l;
}
__device__ __forceinline__ void ldm4(uint32_t* r, uint32_t addr) {
    asm volatile("ldmatrix.sync.aligned.m8n8.x4.shared.b16 {%0,%1,%2,%3}, [%4];"
        : "=r"(r[0]), "=r"(r[1]), "=r"(r[2]), "=r"(r[3]) : "r"(addr));
}
__device__ __forceinline__ void mma16816(float* c, const uint32_t* a, const uint32_t* b) {
    asm volatile("mma.sync.aligned.m16n8k16.row.col.f32.bf16.bf16.f32 "
        "{%0,%1,%2,%3}, {%4,%5,%6,%7}, {%8,%9}, {%0,%1,%2,%3};"
        : "+f"(c[0]), "+f"(c[1]), "+f"(c[2]), "+f"(c[3])
        : "r"(a[0]), "r"(a[1]), "r"(a[2]), "r"(a[3]), "r"(b[0]), "r"(b[1]));
}
__device__ __forceinline__ void cpa16(uint32_t dst, const void* src) {
    asm volatile("cp.async.ca.shared.global [%0], [%1], 16;" :: "r"(dst), "l"(src));
}

__global__ void convert_w1_kernel(const float* __restrict__ W1) {
    int i = blockIdx.x * blockDim.x + threadIdx.x;   // 524288
    float x = W1[i];
    __nv_bfloat16 h = __float2bfloat16(x);
    g_W1h[i] = h;
    g_W1l[i] = __float2bfloat16(x - __bfloat162float(h));
}

// right fp32 [B][30][512] -> bf16 hi/lo [B][32][512], rows 30,31 zero
__global__ void convert_right_kernel(const float* __restrict__ right) {
    int seg = blockIdx.x * blockDim.x + threadIdx.x;   // 2048*32*64 = 4194304
    int b   = seg >> 11;
    int rem = seg & 2047;
    int l   = rem >> 6;
    int sg  = rem & 63;
    uint4 hv = make_uint4(0u, 0u, 0u, 0u), lv = hv;
    if (l < L_) {
        const float4* src = (const float4*)(right + (((size_t)b * L_ + l) * D_) + sg * 8);
        float4 x0 = src[0], x1 = src[1];
        cvt2(x0.x, x0.y, hv.x, lv.x);
        cvt2(x0.z, x0.w, hv.y, lv.y);
        cvt2(x1.x, x1.y, hv.z, lv.z);
        cvt2(x1.z, x1.w, hv.w, lv.w);
    }
    size_t off = ((size_t)b * 32 + l) * D_ + sg * 8;
    *(uint4*)(g_rh + off) = hv;
    *(uint4*)(g_rl + off) = lv;
}

__global__ __launch_bounds__(THREADS, 1)
void fused_attn_mma_kernel(const float* __restrict__ left,
                           const float* __restrict__ right,
                           const int*   __restrict__ mask,
                           const float* __restrict__ W1,
                           const float* __restrict__ W2,
                           const float* __restrict__ W_o,
                           const float* __restrict__ b_o,
                           const float* __restrict__ scales_blk,
                           const float* __restrict__ W_c,
                           const float* __restrict__ b_c,
                           const float* __restrict__ scale_fin,
                           const float* __restrict__ W_aoa,
                           const float* __restrict__ b_aoa,
                           float* __restrict__ out)
{
    extern __shared__ char smemc[];
    float* mf   = (float*)(smemc + SOFF_MISC);
    float* lp   = mf + FOFF_LP;
    float* w2s  = mf + FOFF_W2S;
    float* gs   = mf + FOFF_GS;
    float* xb   = mf + FOFF_XB;
    float* cred = mf + FOFF_CRED;
    float* linS = mf + FOFF_LIN;
    float* evdS = mf + FOFF_EVD;
    float* awS  = mf + FOFF_AW;
    float* aw2S = mf + FOFF_AW2;
    float* gg   = mf + FOFF_GG;
    int*   mk   = (int*)(mf + FOFF_MK);
    float* sc   = mf + FOFF_SC;

    const int b4   = blockIdx.x * 4;
    const int t    = threadIdx.x;
    const int w    = t >> 5;
    const int lane = t & 31;
    const uint32_t smem_u = s2u(smemc);

    // ---------------- Phase 0 ----------------
    ((float4*)w2s)[t] = ((const float4*)W2)[t];
    if (t < 120) {
        int bb = t / 30, l = t % 30;
        mk[bb * 32 + l] = mask[(b4 + bb) * L_ + l];
    }
    if (t < 512) linS[t] = 0.f;
    if (t < 128) xb[t] = 1.f;
    __syncthreads();
    if (t < 4) {
        int v = 0;
        for (int l = 0; l < L_; l++) v += mk[t * 32 + l];
        sc[t] = (float)v;
    }

    // ---------------- Phase 1: lp (left projection, fp32) ----------------
    {
        const float4* W14 = (const float4*)W1;
        const float4* lf4 = (const float4*)left;
        for (int j = 0; j < 32; j++) {
            int o = w + 16 * j;
            float a0 = 0.f, a1 = 0.f, a2 = 0.f, a3 = 0.f;
            #pragma unroll
            for (int c = 0; c < 4; c++) {
                float4 wv = W14[(size_t)o * 256 + c * 32 + lane];
                float4 l0 = lf4[(size_t)(b4 + 0) * 128 + c * 32 + lane];
                float4 l1 = lf4[(size_t)(b4 + 1) * 128 + c * 32 + lane];
                float4 l2 = lf4[(size_t)(b4 + 2) * 128 + c * 32 + lane];
                float4 l3 = lf4[(size_t)(b4 + 3) * 128 + c * 32 + lane];
                a0 += wv.x * l0.x + wv.y * l0.y + wv.z * l0.z + wv.w * l0.w;
                a1 += wv.x * l1.x + wv.y * l1.y + wv.z * l1.z + wv.w * l1.w;
                a2 += wv.x * l2.x + wv.y * l2.y + wv.z * l2.z + wv.w * l2.w;
                a3 += wv.x * l3.x + wv.y * l3.y + wv.z * l3.z + wv.w * l3.w;
            }
            #pragma unroll
            for (int s = 16; s; s >>= 1) {
                a0 += __shfl_xor_sync(0xffffffffu, a0, s);
                a1 += __shfl_xor_sync(0xffffffffu, a1, s);
                a2 += __shfl_xor_sync(0xffffffffu, a2, s);
                a3 += __shfl_xor_sync(0xffffffffu, a3, s);
            }
            if (lane == 0) {
                lp[0 * 512 + o] = a0; lp[1 * 512 + o] = a1;
                lp[2 * 512 + o] = a2; lp[3 * 512 + o] = a3;
            }
        }
    }

    // ---------------- Phase 2: Gram matrices ----------------
    for (int bb = 0; bb < 4; bb++) {
        const float4* rbase = (const float4*)(right + (size_t)(b4 + bb) * L_ * D_);
        float* gsb = gs + bb * 900;
        for (int p = w; p < 465; p += 16) {
            int q = 0, rem = p;
            while (rem >= L_ - q) { rem -= L_ - q; q++; }
            int k2 = q + rem;
            const float4* r1 = rbase + q  * 128;
            const float4* r2 = rbase + k2 * 128;
            float a = 0.f;
            #pragma unroll
            for (int c = 0; c < 4; c++) {
                float4 x = r1[c * 32 + lane];
                float4 y = r2[c * 32 + lane];
                a += x.x * y.x + x.y * y.y + x.z * y.z + x.w * y.w;
            }
            #pragma unroll
            for (int s = 16; s; s >>= 1) a += __shfl_xor_sync(0xffffffffu, a, s);
            if (lane == 0) { gsb[q * 30 + k2] = a; gsb[k2 * 30 + q] = a; }
        }
    }
    __syncthreads();

    // ---------------- Phase 3: EvdCred + evd ----------------
    const float inv_sqrt_d = 1.f / sqrtf((float)D_);
    {
        int bb = t >> 5, l = t & 31;
        bool act = (t < 128) && (l < 30);
        for (int it = 0; it < ITER_; it++) {
            float nx = 0.f;
            if (act) {
                float ci = inv_sqrt_d * scales_blk[it];
                float s = 0.f;
                const float* gsb = gs + bb * 900 + l * 30;
                for (int k = 0; k < L_; k++)
                    if (mk[bb * 32 + k]) s += gsb[k] * xb[bb * 32 + k];
                cred[bb * 32 + l] = ci * s / sc[bb];
            }
            __syncthreads();
            if (act) {
                float y = b_o[it * L_ + l];
                const float* wo_ = W_o + it * L_ * L_ + l * L_;
                for (int q = 0; q < L_; q++) y += cred[bb * 32 + q] * wo_[q];
                nx = tanhf(expf(y));
            }
            __syncthreads();
            if (act) xb[bb * 32 + l] = nx;
            __syncthreads();
        }
    }
    if (t < 480) {
        int bb = t / 120, rem = t % 120;
        int l = rem >> 2, h = rem & 3;
        float cf = inv_sqrt_d * scale_fin[0];
        const float* wc = W_c + h * L_;
        const float* gsb = gs + bb * 900 + l * 30;
        float s = 0.f;
        for (int k = 0; k < L_; k++) s += gsb[k] * xb[bb * 32 + k] * wc[k];
        evdS[bb * 128 + l * 4 + h] = tanhf(expf(cf * s + b_c[h]));
    }

    // ---------------- Phase 4: pipelined tensor GEMM ----------------
    // warp tile 32x32: wm = w&3 (rows), wn = w>>2 (cols in the 128-wide pass)
    const int wm = w & 3;
    const int wn = w >> 2;
    const int mi   = lane >> 3;
    const int rA0  = wm * 32 + (mi & 1) * 8 + (lane & 7);
    const int kA8  = mi >> 1;                 // A k8-block select
    const int rB0  = wn * 32 + (lane >> 4) * 8 + (lane & 7);
    const int kB8  = mi & 1;                  // B k8-block select
    const int g    = lane >> 2;
    const int ncol = (lane & 3) * 2;

    float linp[4][4];
    #pragma unroll
    for (int i = 0; i < 4; i++)
        #pragma unroll
        for (int h = 0; h < 4; h++) linp[i][h] = 0.f;

    // stage-issue lambda: iteration it -> (nh = it>>3, kc = it&7), buffer it&1
    auto issue = [&](int it) {
        int s = it & 1, nh = it >> 3, kc = it & 7;
        uint32_t base = smem_u + s * STAGEB;
        #pragma unroll
        for (int r = 0; r < 2; r++) {
            int c = t + r * 512;
            int row = c >> 3, ck = c & 7;
            uint32_t doff = (uint32_t)(row * 128 + ((ck ^ (row & 7)) << 4));
            size_t aoff = ((size_t)(b4 * 32 + row)) * 512 + kc * 64 + ck * 8;
            size_t boff = ((size_t)(nh * 128 + row)) * 1024 + 512 + kc * 64 + ck * 8;
            cpa16(base + 0 * TILE + doff, g_rh  + aoff);
            cpa16(base + 1 * TILE + doff, g_rl  + aoff);
            cpa16(base + 2 * TILE + doff, g_W1h + boff);
            cpa16(base + 3 * TILE + doff, g_W1l + boff);
        }
        asm volatile("cp.async.commit_group;");
    };

    issue(0);
    for (int nh = 0; nh < 4; nh++) {
        float acc[2][4][4];
        #pragma unroll
        for (int i = 0; i < 2; i++)
            #pragma unroll
            for (int j = 0; j < 4; j++)
                #pragma unroll
                for (int c = 0; c < 4; c++) acc[i][j][c] = 0.f;

        for (int kc = 0; kc < 8; kc++) {
            int it = nh * 8 + kc;
            if (it + 1 < 32) {
                issue(it + 1);
                asm volatile("cp.async.wait_group 1;" ::: "memory");
            } else {
                asm volatile("cp.async.wait_group 0;" ::: "memory");
            }
            __syncthreads();

            uint32_t base = smem_u + (it & 1) * STAGEB;
            uint32_t uAh = base, uAl = base + TILE, uBh = base + 2 * TILE, uBl = base + 3 * TILE;

            #pragma unroll
            for (int ks = 0; ks < 4; ks++) {
                uint32_t ah[2][4], al[2][4], bh[2][4], bl[2][4];
                #pragma unroll
                for (int mi2 = 0; mi2 < 2; mi2++) {
                    int row = rA0 + mi2 * 16;
                    int ck  = ks * 2 + kA8;
                    uint32_t off = (uint32_t)(row * 128 + ((ck ^ (row & 7)) << 4));
                    ldm4(ah[mi2], uAh + off);
                    ldm4(al[mi2], uAl + off);
                }
                #pragma unroll
                for (int pr = 0; pr < 2; pr++) {
                    int row = rB0 + pr * 16;
                    int ck  = ks * 2 + kB8;
                    uint32_t off = (uint32_t)(row * 128 + ((ck ^ (row & 7)) << 4));
                    ldm4(bh[pr], uBh + off);
                    ldm4(bl[pr], uBl + off);
                }
                #pragma unroll
                for (int mi2 = 0; mi2 < 2; mi2++) {
                    #pragma unroll
                    for (int pr = 0; pr < 2; pr++) {
                        mma16816(acc[mi2][pr * 2],     ah[mi2], &bh[pr][0]);
                        mma16816(acc[mi2][pr * 2 + 1], ah[mi2], &bh[pr][2]);
                        mma16816(acc[mi2][pr * 2],     ah[mi2], &bl[pr][0]);
                        mma16816(acc[mi2][pr * 2 + 1], ah[mi2], &bl[pr][2]);
                        mma16816(acc[mi2][pr * 2],     al[mi2], &bh[pr][0]);
                        mma16816(acc[mi2][pr * 2 + 1], al[mi2], &bh[pr][2]);
                    }
                }
            }
            __syncthreads();   // tiles consumed; next issue may overwrite
        }

        // epilogue for this nh: tanh + W2 contraction
        #pragma unroll
        for (int mi2 = 0; mi2 < 2; mi2++) {
            #pragma unroll
            for (int ni = 0; ni < 4; ni++) {
                #pragma unroll
                for (int c = 0; c < 4; c++) {
                    int row = wm * 32 + mi2 * 16 + g + (c >> 1) * 8;
                    int l = row & 31;
                    if (l < 30) {
                        int bb = row >> 5;
                        int o = nh * 128 + wn * 32 + ni * 8 + ncol + (c & 1);
                        float hv = tanhf(lp[bb * 512 + o] + acc[mi2][ni][c]);
                        int ridx = mi2 * 2 + (c >> 1);
                        linp[ridx][0] += w2s[o] * hv;
                        linp[ridx][1] += w2s[512 + o] * hv;
                        linp[ridx][2] += w2s[1024 + o] * hv;
                        linp[ridx][3] += w2s[1536 + o] * hv;
                    }
                }
            }
        }
    }

    // reduce over the 4 lanes sharing each row, then smem atomics
    #pragma unroll
    for (int ridx = 0; ridx < 4; ridx++) {
        #pragma unroll
        for (int h = 0; h < 4; h++) {
            float p = linp[ridx][h];
            p += __shfl_xor_sync(0xffffffffu, p, 1);
            p += __shfl_xor_sync(0xffffffffu, p, 2);
            if ((lane & 3) == 0) {
                int row = wm * 32 + (ridx >> 1) * 16 + g + (ridx & 1) * 8;
                if ((row & 31) < 30) atomicAdd(&linS[row * 4 + h], p);
            }
        }
    }
    __syncthreads();

    // ---------------- Phase 5: masked softmax ----------------
    if (t < 16) {
        int bb = t >> 2, h = t & 3;
        float m = -1e30f;
        for (int l = 0; l < L_; l++)
            if (mk[bb * 32 + l]) m = fmaxf(m, linS[(bb * 32 + l) * 4 + h]);
        float ssum = 0.f;
        for (int l = 0; l < L_; l++) {
            float e = mk[bb * 32 + l] ? expf(linS[(bb * 32 + l) * 4 + h] - m) : 0.f;
            awS[bb * 128 + l * 4 + h] = e;
            ssum += e;
        }
        float inv = 1.f / ssum;
        for (int l = 0; l < L_; l++) awS[bb * 128 + l * 4 + h] *= inv;
    }
    __syncthreads();

    // ---------------- Phase 6: AoA (GLU) ----------------
    for (int idx = t; idx < 960; idx += THREADS) {
        int bb = idx / 240, rem = idx % 240;
        int l = rem >> 3, j = rem & 7;
        float y = b_aoa[j];
        const float* wa = W_aoa + j * 8;
        #pragma unroll
        for (int m2 = 0; m2 < 8; m2++) {
            float c = (m2 < 4) ? awS[bb * 128 + l * 4 + m2]
                               : evdS[bb * 128 + l * 4 + (m2 - 4)];
            y += wa[m2] * c;
        }
        gg[bb * 240 + l * 8 + j] = y;
    }
    __syncthreads();
    if (t < 480) {
        int bb = t / 120, rem = t % 120;
        int l = rem >> 2, h = rem & 3;
        float a  = gg[bb * 240 + l * 8 + h];
        float bv = gg[bb * 240 + l * 8 + 4 + h];
        aw2S[bb * 128 + l * 4 + h] = a / (1.f + expf(-bv));
    }
    __syncthreads();

    // ---------------- Phase 7: attended ----------------
    {
        int bb = t >> 7, d = (t & 127) * 4;
        const float* rb = right + (size_t)(b4 + bb) * L_ * D_;
        float4 o0 = make_float4(0.f, 0.f, 0.f, 0.f);
        float4 o1 = o0, o2 = o0, o3 = o0;
        for (int l = 0; l < L_; l++) {
            float4 r = *(const float4*)(rb + l * D_ + d);
            float v0 = aw2S[bb * 128 + l * 4 + 0];
            float v1 = aw2S[bb * 128 + l * 4 + 1];
            float v2 = aw2S[bb * 128 + l * 4 + 2];
            float v3 = aw2S[bb * 128 + l * 4 + 3];
            o0.x += r.x * v0; o0.y += r.x * v1; o0.z += r.x * v2; o0.w += r.x * v3;
            o1.x += r.y * v0; o1.y += r.y * v1; o1.z += r.y * v2; o1.w += r.y * v3;
            o2.x += r.z * v0; o2.y += r.z * v1; o2.z += r.z * v2; o2.w += r.z * v3;
            o3.x += r.w * v0; o3.y += r.w * v1; o3.z += r.w * v2; o3.w += r.w * v3;
        }
        float4* ob = (float4*)out + (size_t)(b4 + bb) * 512 + d;
        ob[0] = o0; ob[1] = o1; ob[2] = o2; ob[3] = o3;
    }

    // ---------------- Phase 8: second output ----------------
    for (int idx = t; idx < 960; idx += THREADS) {
        int bb = idx / 240, rem = idx % 240;
        int l = rem >> 3, j = rem & 7;
        float v = (j < 4) ? evdS[bb * 128 + l * 4 + j]
                          : aw2S[bb * 128 + l * 4 + (j - 4)];
        out[(size_t)B_ * D_ * H_ + (size_t)(b4 + bb) * (L_ * 2 * H_) + l * 8 + j] = v;
    }
}

extern "C" void kernel_launch(void* const* d_in, const int* in_sizes, int n_in,
                              void* d_out, int out_size)
{
    const float* left       = (const float*)d_in[0];
    const float* right      = (const float*)d_in[1];
    const int*   mask       = (const int*)  d_in[2];
    const float* W1         = (const float*)d_in[3];
    const float* W2         = (const float*)d_in[4];
    const float* W_o        = (const float*)d_in[5];
    const float* b_o        = (const float*)d_in[6];
    const float* scales_blk = (const float*)d_in[7];
    const float* W_c        = (const float*)d_in[8];
    const float* b_c        = (const float*)d_in[9];
    const float* scale_fin  = (const float*)d_in[10];
    const float* W_aoa      = (const float*)d_in[11];
    const float* b_aoa      = (const float*)d_in[12];
    float* out = (float*)d_out;

    convert_w1_kernel<<<2048, 256>>>(W1);
    convert_right_kernel<<<8192, 512>>>(right);

    cudaFuncSetAttribute(fused_attn_mma_kernel,
                         cudaFuncAttributeMaxDynamicSharedMemorySize, SMEM_BYTES);
    fused_attn_mma_kernel<<<B_ / 4, THREADS, SMEM_BYTES>>>(left, right, mask, W1, W2,
                                                           W_o, b_o, scales_blk, W_c,
                                                           b_c, scale_fin, W_aoa, b_aoa,
                                                           out);
}

// round 10
// speedup vs baseline: 3.1624x; 1.1252x over previous
#include <cuda_runtime.h>
#include <cuda_fp16.h>
#include <cstdint>
#include <math.h>

#define B_    2048
#define L_    30
#define D_    512
#define X_    512
#define H_    4
#define OUT_  512
#define ITER_ 4

#define THREADS 512
// tiles: 128 rows x 64 fp16 cols (128B/row), XOR swizzle (chunk ^ (row&7))
#define TILE    16384
#define STAGEB  49152          // Ah, Al, Bh per stage
#define NSTAGES 3
#define SOFF_MISC (NSTAGES * STAGEB)   // 147456

// misc float offsets
#define FOFF_LP   0            // 4 x 512
#define FOFF_W2S  2048         // 2048
#define FOFF_GS   4096         // 4 x 900
#define FOFF_XB   7696         // 128
#define FOFF_CRED 7824         // 128
#define FOFF_LIN  7952         // 512
#define FOFF_EVD  8464         // 512
#define FOFF_AW   8976         // 512
#define FOFF_AW2  9488         // 512
#define FOFF_GG   10000        // 960
#define FOFF_MK   10960        // 128 ints
#define FOFF_SC   11088        // 8
#define MISC_FLOATS 11096
#define SMEM_BYTES (SOFF_MISC + MISC_FLOATS * 4)   // 191840

#define RSEG  4194304          // 2048*32*64 right segments (8 floats each)
#define WSEG  32768            // 512*64 W1 segments (8 floats each)

// preconverted operands (fp16)
__device__ __align__(16) __half g_W1h[OUT_ * 512];               // W1 right half, single fp16
__device__ __align__(16) __half g_rh[(size_t)B_ * 32 * D_];      // right hi
__device__ __align__(16) __half g_rl[(size_t)B_ * 32 * D_];      // right lo (residual)

__device__ __forceinline__ uint32_t s2u(const void* p) {
    return (uint32_t)__cvta_generic_to_shared(p);
}
__device__ __forceinline__ void cvt2h(float a, float b, uint32_t& hi, uint32_t& lo) {
    __half2 h = __floats2half2_rn(a, b);
    float ra = a - __half2float(h.x);
    float rb = b - __half2float(h.y);
    __half2 l = __floats2half2_rn(ra, rb);
    hi = *(uint32_t*)&h;
    lo = *(uint32_t*)&l;
}
__device__ __forceinline__ void ldm4(uint32_t* r, uint32_t addr) {
    asm volatile("ldmatrix.sync.aligned.m8n8.x4.shared.b16 {%0,%1,%2,%3}, [%4];"
        : "=r"(r[0]), "=r"(r[1]), "=r"(r[2]), "=r"(r[3]) : "r"(addr));
}
__device__ __forceinline__ void mma16816(float* c, const uint32_t* a, const uint32_t* b) {
    asm volatile("mma.sync.aligned.m16n8k16.row.col.f32.f16.f16.f32 "
        "{%0,%1,%2,%3}, {%4,%5,%6,%7}, {%8,%9}, {%0,%1,%2,%3};"
        : "+f"(c[0]), "+f"(c[1]), "+f"(c[2]), "+f"(c[3])
        : "r"(a[0]), "r"(a[1]), "r"(a[2]), "r"(a[3]), "r"(b[0]), "r"(b[1]));
}
__device__ __forceinline__ void cpa16(uint32_t dst, const void* src) {
    asm volatile("cp.async.ca.shared.global [%0], [%1], 16;" :: "r"(dst), "l"(src));
}

// merged converter: right fp32 -> fp16 hi/lo [B][32][512] (rows 30,31 zero),
// W1 right-half fp32 -> fp16 single
__global__ void convert_all_kernel(const float* __restrict__ W1,
                                   const float* __restrict__ right) {
    int i = blockIdx.x * blockDim.x + threadIdx.x;
    if (i < RSEG) {
        int b   = i >> 11;
        int rem = i & 2047;
        int l   = rem >> 6;
        int sg  = rem & 63;
        uint4 hv = make_uint4(0u, 0u, 0u, 0u), lv = hv;
        if (l < L_) {
            const float4* src = (const float4*)(right + (((size_t)b * L_ + l) * D_) + sg * 8);
            float4 x0 = src[0], x1 = src[1];
            cvt2h(x0.x, x0.y, hv.x, lv.x);
            cvt2h(x0.z, x0.w, hv.y, lv.y);
            cvt2h(x1.x, x1.y, hv.z, lv.z);
            cvt2h(x1.z, x1.w, hv.w, lv.w);
        }
        size_t off = ((size_t)b * 32 + l) * D_ + sg * 8;
        *(uint4*)(g_rh + off) = hv;
        *(uint4*)(g_rl + off) = lv;
    } else if (i < RSEG + WSEG) {
        int j = i - RSEG;
        int o = j >> 6, kk = (j & 63) << 3;
        const float4* src = (const float4*)(W1 + (size_t)o * 1024 + 512 + kk);
        float4 x0 = src[0], x1 = src[1];
        __half2 h0 = __floats2half2_rn(x0.x, x0.y);
        __half2 h1 = __floats2half2_rn(x0.z, x0.w);
        __half2 h2 = __floats2half2_rn(x1.x, x1.y);
        __half2 h3 = __floats2half2_rn(x1.z, x1.w);
        uint4 hv;
        hv.x = *(uint32_t*)&h0; hv.y = *(uint32_t*)&h1;
        hv.z = *(uint32_t*)&h2; hv.w = *(uint32_t*)&h3;
        *(uint4*)(g_W1h + (size_t)o * 512 + kk) = hv;
    }
}

__global__ __launch_bounds__(THREADS, 1)
void fused_attn_mma_kernel(const float* __restrict__ left,
                           const float* __restrict__ right,
                           const int*   __restrict__ mask,
                           const float* __restrict__ W1,
                           const float* __restrict__ W2,
                           const float* __restrict__ W_o,
                           const float* __restrict__ b_o,
                           const float* __restrict__ scales_blk,
                           const float* __restrict__ W_c,
                           const float* __restrict__ b_c,
                           const float* __restrict__ scale_fin,
                           const float* __restrict__ W_aoa,
                           const float* __restrict__ b_aoa,
                           float* __restrict__ out)
{
    extern __shared__ char smemc[];
    float* mf   = (float*)(smemc + SOFF_MISC);
    float* lp   = mf + FOFF_LP;
    float* w2s  = mf + FOFF_W2S;
    float* gs   = mf + FOFF_GS;
    float* xb   = mf + FOFF_XB;
    float* cred = mf + FOFF_CRED;
    float* linS = mf + FOFF_LIN;
    float* evdS = mf + FOFF_EVD;
    float* awS  = mf + FOFF_AW;
    float* aw2S = mf + FOFF_AW2;
    float* gg   = mf + FOFF_GG;
    int*   mk   = (int*)(mf + FOFF_MK);
    float* sc   = mf + FOFF_SC;

    const int b4   = blockIdx.x * 4;
    const int t    = threadIdx.x;
    const int w    = t >> 5;
    const int lane = t & 31;
    const uint32_t smem_u = s2u(smemc);

    // ---------------- Phase 0 ----------------
    ((float4*)w2s)[t] = ((const float4*)W2)[t];
    if (t < 120) {
        int bb = t / 30, l = t % 30;
        mk[bb * 32 + l] = mask[(b4 + bb) * L_ + l];
    }
    if (t < 512) linS[t] = 0.f;
    if (t < 128) xb[t] = 1.f;
    __syncthreads();
    if (t < 4) {
        int v = 0;
        for (int l = 0; l < L_; l++) v += mk[t * 32 + l];
        sc[t] = (float)v;
    }

    // ---------------- Phase 1: lp (left projection, fp32) ----------------
    {
        const float4* W14 = (const float4*)W1;
        const float4* lf4 = (const float4*)left;
        for (int j = 0; j < 32; j++) {
            int o = w + 16 * j;
            float a0 = 0.f, a1 = 0.f, a2 = 0.f, a3 = 0.f;
            #pragma unroll
            for (int c = 0; c < 4; c++) {
                float4 wv = W14[(size_t)o * 256 + c * 32 + lane];
                float4 l0 = lf4[(size_t)(b4 + 0) * 128 + c * 32 + lane];
                float4 l1 = lf4[(size_t)(b4 + 1) * 128 + c * 32 + lane];
                float4 l2 = lf4[(size_t)(b4 + 2) * 128 + c * 32 + lane];
                float4 l3 = lf4[(size_t)(b4 + 3) * 128 + c * 32 + lane];
                a0 += wv.x * l0.x + wv.y * l0.y + wv.z * l0.z + wv.w * l0.w;
                a1 += wv.x * l1.x + wv.y * l1.y + wv.z * l1.z + wv.w * l1.w;
                a2 += wv.x * l2.x + wv.y * l2.y + wv.z * l2.z + wv.w * l2.w;
                a3 += wv.x * l3.x + wv.y * l3.y + wv.z * l3.z + wv.w * l3.w;
            }
            #pragma unroll
            for (int s = 16; s; s >>= 1) {
                a0 += __shfl_xor_sync(0xffffffffu, a0, s);
                a1 += __shfl_xor_sync(0xffffffffu, a1, s);
                a2 += __shfl_xor_sync(0xffffffffu, a2, s);
                a3 += __shfl_xor_sync(0xffffffffu, a3, s);
            }
            if (lane == 0) {
                lp[0 * 512 + o] = a0; lp[1 * 512 + o] = a1;
                lp[2 * 512 + o] = a2; lp[3 * 512 + o] = a3;
            }
        }
    }

    // ---------------- Phase 2: Gram matrices ----------------
    for (int bb = 0; bb < 4; bb++) {
        const float4* rbase = (const float4*)(right + (size_t)(b4 + bb) * L_ * D_);
        float* gsb = gs + bb * 900;
        for (int p = w; p < 465; p += 16) {
            int q = 0, rem = p;
            while (rem >= L_ - q) { rem -= L_ - q; q++; }
            int k2 = q + rem;
            const float4* r1 = rbase + q  * 128;
            const float4* r2 = rbase + k2 * 128;
            float a = 0.f;
            #pragma unroll
            for (int c = 0; c < 4; c++) {
                float4 x = r1[c * 32 + lane];
                float4 y = r2[c * 32 + lane];
                a += x.x * y.x + x.y * y.y + x.z * y.z + x.w * y.w;
            }
            #pragma unroll
            for (int s = 16; s; s >>= 1) a += __shfl_xor_sync(0xffffffffu, a, s);
            if (lane == 0) { gsb[q * 30 + k2] = a; gsb[k2 * 30 + q] = a; }
        }
    }
    __syncthreads();

    // ---------------- Phase 3: EvdCred + evd ----------------
    const float inv_sqrt_d = 1.f / sqrtf((float)D_);
    {
        int bb = t >> 5, l = t & 31;
        bool act = (t < 128) && (l < 30);
        for (int it = 0; it < ITER_; it++) {
            float nx = 0.f;
            if (act) {
                float ci = inv_sqrt_d * scales_blk[it];
                float s = 0.f;
                const float* gsb = gs + bb * 900 + l * 30;
                for (int k = 0; k < L_; k++)
                    if (mk[bb * 32 + k]) s += gsb[k] * xb[bb * 32 + k];
                cred[bb * 32 + l] = ci * s / sc[bb];
            }
            __syncthreads();
            if (act) {
                float y = b_o[it * L_ + l];
                const float* wo_ = W_o + it * L_ * L_ + l * L_;
                for (int q = 0; q < L_; q++) y += cred[bb * 32 + q] * wo_[q];
                nx = tanhf(expf(y));
            }
            __syncthreads();
            if (act) xb[bb * 32 + l] = nx;
            __syncthreads();
        }
    }
    if (t < 480) {
        int bb = t / 120, rem = t % 120;
        int l = rem >> 2, h = rem & 3;
        float cf = inv_sqrt_d * scale_fin[0];
        const float* wc = W_c + h * L_;
        const float* gsb = gs + bb * 900 + l * 30;
        float s = 0.f;
        for (int k = 0; k < L_; k++) s += gsb[k] * xb[bb * 32 + k] * wc[k];
        evdS[bb * 128 + l * 4 + h] = tanhf(expf(cf * s + b_c[h]));
    }

    // ---------------- Phase 4: pipelined tensor GEMM (fp16 2-term) ----------------
    // warp tile 32x32: wm = w&3 (rows), wn = w>>2 (cols of the 128-wide pass)
    const int wm = w & 3;
    const int wn = w >> 2;
    const int mi   = lane >> 3;
    const int rA0  = wm * 32 + (mi & 1) * 8 + (lane & 7);
    const int kA8  = mi >> 1;
    const int rB0  = wn * 32 + (lane >> 4) * 8 + (lane & 7);
    const int kB8  = mi & 1;
    const int g    = lane >> 2;
    const int ncol = (lane & 3) * 2;

    float linp[4][4];
    #pragma unroll
    for (int i = 0; i < 4; i++)
        #pragma unroll
        for (int h = 0; h < 4; h++) linp[i][h] = 0.f;

    // issue stage it -> buffer it % 3: tiles Ah (g_rh), Al (g_rl), Bh (g_W1h)
    auto issue = [&](int it) {
        int s = it % NSTAGES, nh = it >> 3, kc = it & 7;
        uint32_t base = smem_u + s * STAGEB;
        #pragma unroll
        for (int r = 0; r < 2; r++) {
            int c = t + r * 512;
            int row = c >> 3, ck = c & 7;
            uint32_t doff = (uint32_t)(row * 128 + ((ck ^ (row & 7)) << 4));
            size_t aoff = ((size_t)(b4 * 32 + row)) * 512 + kc * 64 + ck * 8;
            size_t boff = ((size_t)(nh * 128 + row)) * 512 + kc * 64 + ck * 8;
            cpa16(base + 0 * TILE + doff, g_rh  + aoff);
            cpa16(base + 1 * TILE + doff, g_rl  + aoff);
            cpa16(base + 2 * TILE + doff, g_W1h + boff);
        }
        asm volatile("cp.async.commit_group;");
    };

    issue(0);
    issue(1);
    for (int nh = 0; nh < 4; nh++) {
        float acc[2][4][4];
        #pragma unroll
        for (int i = 0; i < 2; i++)
            #pragma unroll
            for (int j = 0; j < 4; j++)
                #pragma unroll
                for (int c = 0; c < 4; c++) acc[i][j][c] = 0.f;

        for (int kc = 0; kc < 8; kc++) {
            int it = nh * 8 + kc;
            if (it < 31) {
                asm volatile("cp.async.wait_group 1;" ::: "memory");
            } else {
                asm volatile("cp.async.wait_group 0;" ::: "memory");
            }
            __syncthreads();          // stage `it` visible; compute it-1 done everywhere
            if (it + 2 < 32) issue(it + 2);

            uint32_t base = smem_u + (it % NSTAGES) * STAGEB;
            uint32_t uAh = base, uAl = base + TILE, uBh = base + 2 * TILE;

            #pragma unroll
            for (int ks = 0; ks < 4; ks++) {
                uint32_t ah[2][4], al[2][4], bh[2][4];
                #pragma unroll
                for (int mi2 = 0; mi2 < 2; mi2++) {
                    int row = rA0 + mi2 * 16;
                    int ck  = ks * 2 + kA8;
                    uint32_t off = (uint32_t)(row * 128 + ((ck ^ (row & 7)) << 4));
                    ldm4(ah[mi2], uAh + off);
                    ldm4(al[mi2], uAl + off);
                }
                #pragma unroll
                for (int pr = 0; pr < 2; pr++) {
                    int row = rB0 + pr * 16;
                    int ck  = ks * 2 + kB8;
                    uint32_t off = (uint32_t)(row * 128 + ((ck ^ (row & 7)) << 4));
                    ldm4(bh[pr], uBh + off);
                }
                // hi-term mmas first (8), then lo-term (8): long dependency spacing
                #pragma unroll
                for (int mi2 = 0; mi2 < 2; mi2++) {
                    #pragma unroll
                    for (int pr = 0; pr < 2; pr++) {
                        mma16816(acc[mi2][pr * 2],     ah[mi2], &bh[pr][0]);
                        mma16816(acc[mi2][pr * 2 + 1], ah[mi2], &bh[pr][2]);
                    }
                }
                #pragma unroll
                for (int mi2 = 0; mi2 < 2; mi2++) {
                    #pragma unroll
                    for (int pr = 0; pr < 2; pr++) {
                        mma16816(acc[mi2][pr * 2],     al[mi2], &bh[pr][0]);
                        mma16816(acc[mi2][pr * 2 + 1], al[mi2], &bh[pr][2]);
                    }
                }
            }
        }

        // epilogue for this nh: tanh + W2 contraction
        #pragma unroll
        for (int mi2 = 0; mi2 < 2; mi2++) {
            #pragma unroll
            for (int ni = 0; ni < 4; ni++) {
                #pragma unroll
                for (int c = 0; c < 4; c++) {
                    int row = wm * 32 + mi2 * 16 + g + (c >> 1) * 8;
                    int l = row & 31;
                    if (l < 30) {
                        int bb = row >> 5;
                        int o = nh * 128 + wn * 32 + ni * 8 + ncol + (c & 1);
                        float hv = tanhf(lp[bb * 512 + o] + acc[mi2][ni][c]);
                        int ridx = mi2 * 2 + (c >> 1);
                        linp[ridx][0] += w2s[o] * hv;
                        linp[ridx][1] += w2s[512 + o] * hv;
                        linp[ridx][2] += w2s[1024 + o] * hv;
                        linp[ridx][3] += w2s[1536 + o] * hv;
                    }
                }
            }
        }
    }

    // reduce over the 4 lanes sharing each row, then smem atomics
    #pragma unroll
    for (int ridx = 0; ridx < 4; ridx++) {
        #pragma unroll
        for (int h = 0; h < 4; h++) {
            float p = linp[ridx][h];
            p += __shfl_xor_sync(0xffffffffu, p, 1);
            p += __shfl_xor_sync(0xffffffffu, p, 2);
            if ((lane & 3) == 0) {
                int row = wm * 32 + (ridx >> 1) * 16 + g + (ridx & 1) * 8;
                if ((row & 31) < 30) atomicAdd(&linS[row * 4 + h], p);
            }
        }
    }
    __syncthreads();

    // ---------------- Phase 5: masked softmax ----------------
    if (t < 16) {
        int bb = t >> 2, h = t & 3;
        float m = -1e30f;
        for (int l = 0; l < L_; l++)
            if (mk[bb * 32 + l]) m = fmaxf(m, linS[(bb * 32 + l) * 4 + h]);
        float ssum = 0.f;
        for (int l = 0; l < L_; l++) {
            float e = mk[bb * 32 + l] ? expf(linS[(bb * 32 + l) * 4 + h] - m) : 0.f;
            awS[bb * 128 + l * 4 + h] = e;
            ssum += e;
        }
        float inv = 1.f / ssum;
        for (int l = 0; l < L_; l++) awS[bb * 128 + l * 4 + h] *= inv;
    }
    __syncthreads();

    // ---------------- Phase 6: AoA (GLU) ----------------
    for (int idx = t; idx < 960; idx += THREADS) {
        int bb = idx / 240, rem = idx % 240;
        int l = rem >> 3, j = rem & 7;
        float y = b_aoa[j];
        const float* wa = W_aoa + j * 8;
        #pragma unroll
        for (int m2 = 0; m2 < 8; m2++) {
            float c = (m2 < 4) ? awS[bb * 128 + l * 4 + m2]
                               : evdS[bb * 128 + l * 4 + (m2 - 4)];
            y += wa[m2] * c;
        }
        gg[bb * 240 + l * 8 + j] = y;
    }
    __syncthreads();
    if (t < 480) {
        int bb = t / 120, rem = t % 120;
        int l = rem >> 2, h = rem & 3;
        float a  = gg[bb * 240 + l * 8 + h];
        float bv = gg[bb * 240 + l * 8 + 4 + h];
        aw2S[bb * 128 + l * 4 + h] = a / (1.f + expf(-bv));
    }
    __syncthreads();

    // ---------------- Phase 7: attended ----------------
    {
        int bb = t >> 7, d = (t & 127) * 4;
        const float* rb = right + (size_t)(b4 + bb) * L_ * D_;
        float4 o0 = make_float4(0.f, 0.f, 0.f, 0.f);
        float4 o1 = o0, o2 = o0, o3 = o0;
        for (int l = 0; l < L_; l++) {
            float4 r = *(const float4*)(rb + l * D_ + d);
            float v0 = aw2S[bb * 128 + l * 4 + 0];
            float v1 = aw2S[bb * 128 + l * 4 + 1];
            float v2 = aw2S[bb * 128 + l * 4 + 2];
            float v3 = aw2S[bb * 128 + l * 4 + 3];
            o0.x += r.x * v0; o0.y += r.x * v1; o0.z += r.x * v2; o0.w += r.x * v3;
            o1.x += r.y * v0; o1.y += r.y * v1; o1.z += r.y * v2; o1.w += r.y * v3;
            o2.x += r.z * v0; o2.y += r.z * v1; o2.z += r.z * v2; o2.w += r.z * v3;
            o3.x += r.w * v0; o3.y += r.w * v1; o3.z += r.w * v2; o3.w += r.w * v3;
        }
        float4* ob = (float4*)out + (size_t)(b4 + bb) * 512 + d;
        ob[0] = o0; ob[1] = o1; ob[2] = o2; ob[3] = o3;
    }

    // ---------------- Phase 8: second output ----------------
    for (int idx = t; idx < 960; idx += THREADS) {
        int bb = idx / 240, rem = idx % 240;
        int l = rem >> 3, j = rem & 7;
        float v = (j < 4) ? evdS[bb * 128 + l * 4 + j]
                          : aw2S[bb * 128 + l * 4 + (j - 4)];
        out[(size_t)B_ * D_ * H_ + (size_t)(b4 + bb) * (L_ * 2 * H_) + l * 8 + j] = v;
    }
}

extern "C" void kernel_launch(void* const* d_in, const int* in_sizes, int n_in,
                              void* d_out, int out_size)
{
    const float* left       = (const float*)d_in[0];
    const float* right      = (const float*)d_in[1];
    const int*   mask       = (const int*)  d_in[2];
    const float* W1         = (const float*)d_in[3];
    const float* W2         = (const float*)d_in[4];
    const float* W_o        = (const float*)d_in[5];
    const float* b_o        = (const float*)d_in[6];
    const float* scales_blk = (const float*)d_in[7];
    const float* W_c        = (const float*)d_in[8];
    const float* b_c        = (const float*)d_in[9];
    const float* scale_fin  = (const float*)d_in[10];
    const float* W_aoa      = (const float*)d_in[11];
    const float* b_aoa      = (const float*)d_in[12];
    float* out = (float*)d_out;

    convert_all_kernel<<<(RSEG + WSEG) / THREADS, THREADS>>>(W1, right);

    cudaFuncSetAttribute(fused_attn_mma_kernel,
                         cudaFuncAttributeMaxDynamicSharedMemorySize, SMEM_BYTES);
    fused_attn_mma_kernel<<<B_ / 4, THREADS, SMEM_BYTES>>>(left, right, mask, W1, W2,
                                                           W_o, b_o, scales_blk, W_c,
                                                           b_c, scale_fin, W_aoa, b_aoa,
                                                           out);
}